// round 4
// baseline (speedup 1.0000x reference)
#include <cuda_runtime.h>
#include <cuda_bf16.h>

// HMM forward, scaled probability domain.
//   w_t[j] = (sum_i w_{t-1}[i] * exp(trans[i,j])) * inv_norm * exp(emit[j,obs[t]])
//   out    = log(sum_j w_final[j]) + sum log(norm)
//
// 128 persistent CTAs x 256 threads; CTA owns 8 output columns.
// Sync: sign-tag data-as-sync (phase in sign bit; buffer = t&1, sign = (t>>1)&1).
// NEW (R4): the w vector is REPLICATED 8x. Writers store their 8-column chunk
// to all 8 replicas; CTA c polls only replica (c & 7). This cuts per-L2-line
// poll fan-in from 1024 threads to 128 (16 CTAs), eliminating the ~480 cyc/step
// LTS-slice serialization that dominated R1/R3.
//
// Anti-race (distance 3, period 4 = 2 buffers x 2 signs): the writer of step
// t+4 reads all chunks of t+3; CTA c's t+3 chunk write follows (program order)
// c's read of step t. So no granule is overwritten while a reader still wants
// its step-t value.

#define S     1024
#define NOBS  4096
#define TT    8192
#define KCTA  128
#define CCOL  8
#define NTHR  256
#define NREP  8

__device__ __align__(16) float        g_emitT[TT * S];        // exp(emit[j, obs[t]])
__device__ __align__(16) unsigned int g_wrep[NREP][2][S];     // replicated tagged w

__device__ __forceinline__ uint4 ld_vol_v4(const unsigned int* p) {
    uint4 v;
    asm volatile("ld.volatile.global.v4.u32 {%0,%1,%2,%3}, [%4];"
                 : "=r"(v.x), "=r"(v.y), "=r"(v.z), "=r"(v.w) : "l"(p) : "memory");
    return v;
}
__device__ __forceinline__ void st_rel_u32(unsigned int* p, unsigned int v) {
    asm volatile("st.relaxed.gpu.global.u32 [%0], %1;" :: "l"(p), "r"(v) : "memory");
}

// Prologue: gather exp(emit) per timestep; w0 into all replicas (buffer 0, tag 0).
__global__ void hmm_init_kernel(const int* __restrict__ obs,
                                const float* __restrict__ start,
                                const float* __restrict__ emit) {
    long idx = (long)blockIdx.x * blockDim.x + threadIdx.x;
    if (idx >= (long)TT * S) return;
    int t = (int)(idx >> 10);
    int j = (int)(idx & (S - 1));
    float e = expf(emit[(long)j * NOBS + obs[t]]);
    g_emitT[idx] = e;
    if (t == 0) {
        float v = fmaxf(expf(start[j]) * e, 1e-33f);
        unsigned u = __float_as_uint(v);          // sign 0 == phase of t=0
        #pragma unroll
        for (int r = 0; r < NREP; ++r) g_wrep[r][0][j] = u;
    }
}

__global__ void __launch_bounds__(NTHR, 1)
hmm_main_kernel(const float* __restrict__ trans, float* __restrict__ out) {
    __shared__ float red_s[2][NTHR / 32][CCOL];   // per-warp partials, parity-buffered
    __shared__ float max_s[NTHR / 32];

    const int tid  = threadIdx.x;
    const int lane = tid & 31;
    const int wid  = tid >> 5;
    const int cta  = blockIdx.x;
    const int rep  = cta & (NREP - 1);
    const int j0   = cta * CCOL;
    const int i0   = tid << 2;                    // this thread's 4 source states

    // P slice in registers: P[c][u] = exp(trans[i0+u][j0+c]).
    float P[CCOL][4];
    #pragma unroll
    for (int u = 0; u < 4; ++u) {
        #pragma unroll
        for (int c = 0; c < CCOL; ++c)
            P[c][u] = expf(__ldg(&trans[(long)(i0 + u) * S + j0 + c]));
    }

    float e_c = 0.0f, e_n = 0.0f, e_n2 = 0.0f;
    if (tid < CCOL) {
        e_c = __ldg(&g_emitT[1 * S + j0 + tid]);
        e_n = __ldg(&g_emitT[2 * S + j0 + tid]);
    }

    float logscale = 0.0f;    // maintained identically on tid < CCOL

    for (int t = 1; t < TT; ++t) {
        const int      rb    = (t - 1) & 1;
        const int      par   = t & 1;
        const unsigned esbit = (((unsigned)(t - 1) >> 1) & 1u) << 31;
        const unsigned int* gp = &g_wrep[rep][rb][i0];

        // ---- Poll own granule in own replica: the data IS the sync ----
        float w0, w1, w2, w3;
        for (;;) {
            uint4 v = ld_vol_v4(gp);
            unsigned bad = ((v.x ^ esbit) | (v.y ^ esbit) |
                            (v.z ^ esbit) | (v.w ^ esbit)) & 0x80000000u;
            if (!bad) {
                w0 = __uint_as_float(v.x & 0x7fffffffu);
                w1 = __uint_as_float(v.y & 0x7fffffffu);
                w2 = __uint_as_float(v.z & 0x7fffffffu);
                w3 = __uint_as_float(v.w & 0x7fffffffu);
                break;
            }
        }

        // Emission prefetch, two steps deep.
        if (tid < CCOL) {
            int tn = (t + 2 < TT) ? t + 2 : TT - 1;
            e_n2 = __ldg(&g_emitT[tn * S + j0 + tid]);
        }

        // ---- Rescale pre-pass (every 8th step): per-warp max to SMEM ----
        const bool resc = ((t - 1) & 7) == 0;
        if (resc) {
            float m = fmaxf(fmaxf(w0, w1), fmaxf(w2, w3));
            #pragma unroll
            for (int off = 16; off; off >>= 1)
                m = fmaxf(m, __shfl_xor_sync(0xffffffffu, m, off));
            if (lane == 0) max_s[wid] = m;
        }

        // ---- GEMV: 32 FFMA, 8 independent chains ----
        float acc[CCOL];
        #pragma unroll
        for (int c = 0; c < CCOL; ++c)
            acc[c] = w0 * P[c][0] + w1 * P[c][1] + w2 * P[c][2] + w3 * P[c][3];

        #pragma unroll
        for (int off = 16; off; off >>= 1) {
            #pragma unroll
            for (int c = 0; c < CCOL; ++c)
                acc[c] += __shfl_xor_sync(0xffffffffu, acc[c], off);
        }
        if (lane == 0) {
            #pragma unroll
            for (int c = 0; c < CCOL; ++c) red_s[par][wid][c] = acc[c];
        }
        __syncthreads();

        // ---- Finalize: warp0 lanes 0-7 own the CTA's 8 columns ----
        if (tid < CCOL) {
            float inv = 1.0f;
            if (resc) {
                float m = max_s[0];
                #pragma unroll
                for (int ww = 1; ww < NTHR / 32; ++ww) m = fmaxf(m, max_s[ww]);
                inv = 1.0f / m;
                logscale += logf(m);
            }
            float s = 0.0f;
            #pragma unroll
            for (int ww = 0; ww < NTHR / 32; ++ww) s += red_s[par][ww][tid];
            float outv = fmaxf(s * inv * e_c, 1e-33f);
            unsigned tagged = __float_as_uint(outv) | ((((unsigned)t >> 1) & 1u) << 31);
            const int wb = t & 1;
            #pragma unroll
            for (int r = 0; r < NREP; ++r)
                st_rel_u32(&g_wrep[r][wb][j0 + tid], tagged);
            e_c = e_n;
            e_n = e_n2;
        }
    }

    // ---- Epilogue: CTA 0 polls the final vector (its replica) and reduces ----
    if (cta == 0) {
        const unsigned esbit = (((unsigned)(TT - 1) >> 1) & 1u) << 31;
        const unsigned int* gp = &g_wrep[rep][(TT - 1) & 1][i0];
        float w0, w1, w2, w3;
        for (;;) {
            uint4 v = ld_vol_v4(gp);
            unsigned bad = ((v.x ^ esbit) | (v.y ^ esbit) |
                            (v.z ^ esbit) | (v.w ^ esbit)) & 0x80000000u;
            if (!bad) {
                w0 = __uint_as_float(v.x & 0x7fffffffu);
                w1 = __uint_as_float(v.y & 0x7fffffffu);
                w2 = __uint_as_float(v.z & 0x7fffffffu);
                w3 = __uint_as_float(v.w & 0x7fffffffu);
                break;
            }
        }
        float s = w0 + w1 + w2 + w3;
        #pragma unroll
        for (int off = 16; off; off >>= 1)
            s += __shfl_xor_sync(0xffffffffu, s, off);
        __shared__ float fin_s[NTHR / 32];
        if (lane == 0) fin_s[wid] = s;
        __syncthreads();
        if (tid == 0) {
            float tot = 0.0f;
            #pragma unroll
            for (int ww = 0; ww < NTHR / 32; ++ww) tot += fin_s[ww];
            out[0] = logf(tot) + logscale;
        }
    }
}

extern "C" void kernel_launch(void* const* d_in, const int* in_sizes, int n_in,
                              void* d_out, int out_size) {
    const int*   obs   = (const int*)d_in[0];
    const float* start = (const float*)d_in[1];
    const float* trans = (const float*)d_in[2];
    const float* emit  = (const float*)d_in[3];
    float*       out   = (float*)d_out;

    (void)in_sizes; (void)n_in; (void)out_size;

    const int init_blocks = (TT * S + 255) / 256;
    hmm_init_kernel<<<init_blocks, 256>>>(obs, start, emit);
    hmm_main_kernel<<<KCTA, NTHR>>>(trans, out);
}

// round 6
// speedup vs baseline: 1.6352x; 1.6352x over previous
#include <cuda_runtime.h>
#include <cuda_bf16.h>

// HMM forward, scaled probability domain.
//   w_t[j] = (sum_i w_{t-1}[i] * exp(trans[i,j])) * inv_norm * exp(emit[j,obs[t]])
//   out    = log(sum_j w_final[j]) + sum log(norm)
//
// 128 persistent CTAs x 128 threads (4 warps); CTA owns 8 output columns,
// each warp computes 2 FULL columns (no cross-warp partial reduction).
//
// Sync (R5): sign-tag data-as-sync, but polled ONLY by warp 0 of each CTA
// using GPU-scope ld.relaxed (NOT volatile/SYS — that was the 3x regression
// in R3/R4). Warp 0 stages accepted, de-tagged granules into SMEM
// (double-buffered); ONE __syncthreads per step; compute warps read SMEM.
//
// Phase tag: buffer = t&1, sign = (t>>1)&1 (period 4). ABA at distance 4 is
// impossible: a step t+4 store transitively requires every CTA's warp 0 to
// have ACCEPTED step t (t+4 <- staged t+3 <- all t+3 stores <- ... <- each
// CTA's t+1 stores, which follow its own warp 0's accept of step t).
// WAR on SMEM buffers: the single barrier at step s separates warp 0's
// staging(s) from all warps' reads(s); staging(s+2) into the same buffer
// follows bar(s+1), which all warps reach only after their reads(s) retire.

#define S     1024
#define NOBS  4096
#define TT    8192
#define KCTA  128
#define CCOL  8
#define NTHR  128

__device__ __align__(16) float        g_emitT[TT * S];   // exp(emit[j, obs[t]])
__device__ __align__(16) unsigned int g_w[2][S];         // sign-tagged positive floats

__device__ __forceinline__ uint4 ld_rlx_v4(const unsigned int* p) {
    uint4 v;
    asm volatile("ld.relaxed.gpu.global.v4.u32 {%0,%1,%2,%3}, [%4];"
                 : "=r"(v.x), "=r"(v.y), "=r"(v.z), "=r"(v.w) : "l"(p) : "memory");
    return v;
}
__device__ __forceinline__ void st_rlx_u32(unsigned int* p, unsigned int v) {
    asm volatile("st.relaxed.gpu.global.u32 [%0], %1;" :: "l"(p), "r"(v) : "memory");
}

// Prologue: gather exp(emit) per timestep; w0 into buffer 0 with sign tag 0.
__global__ void hmm_init_kernel(const int* __restrict__ obs,
                                const float* __restrict__ start,
                                const float* __restrict__ emit) {
    long idx = (long)blockIdx.x * blockDim.x + threadIdx.x;
    if (idx >= (long)TT * S) return;
    int t = (int)(idx >> 10);
    int j = (int)(idx & (S - 1));
    float e = expf(emit[(long)j * NOBS + obs[t]]);
    g_emitT[idx] = e;
    if (t == 0) {
        float v = fmaxf(expf(start[j]) * e, 1e-33f);
        g_w[0][j] = __float_as_uint(v);      // sign 0 == phase of t=0
    }
}

__global__ void __launch_bounds__(NTHR, 1)
hmm_main_kernel(const float* __restrict__ trans, float* __restrict__ out) {
    __shared__ __align__(16) float w_s[2][S];   // staged de-tagged w, parity buffers
    __shared__ float m_s[2];                    // rescale max, parity buffered

    const int tid  = threadIdx.x;
    const int lane = tid & 31;
    const int wid  = tid >> 5;
    const int cta  = blockIdx.x;
    const int j0   = cta * CCOL;
    const int col0 = j0 + (wid << 1);           // this warp's 2 output columns

    // P slices in registers: P0/P1[k*4+u] = exp(trans[128k + 4*lane + u][col]).
    float P0[32], P1[32];
    #pragma unroll
    for (int k = 0; k < 8; ++k) {
        #pragma unroll
        for (int u = 0; u < 4; ++u) {
            int i = (k << 7) + (lane << 2) + u;
            P0[(k << 2) + u] = expf(__ldg(&trans[(long)i * S + col0]));
            P1[(k << 2) + u] = expf(__ldg(&trans[(long)i * S + col0 + 1]));
        }
    }

    // Emission values for this warp's storer lanes (lane 0 -> col0, lane 1 -> col0+1).
    float e_c = 0.0f, e_n = 0.0f, e_n2 = 0.0f;
    if (lane < 2) {
        e_c = __ldg(&g_emitT[1 * S + col0 + lane]);
        e_n = __ldg(&g_emitT[2 * S + col0 + lane]);
    }

    float logscale = 0.0f;   // tracked identically by every thread

    for (int t = 1; t < TT; ++t) {
        const int      rb    = (t - 1) & 1;          // global read buffer
        const int      par   = t & 1;                // smem/stage parity
        const bool     resc  = ((t - 1) & 7) == 0;
        const unsigned esbit = (((unsigned)(t - 1) >> 1) & 1u) << 31;

        // ---- Warp 0: poll + stage (GPU-scope relaxed loads, tag check) ----
        if (wid == 0) {
            unsigned pend = 0xffu;
            float mloc = 0.0f;
            do {
                #pragma unroll
                for (int k = 0; k < 8; ++k) {
                    if (pend & (1u << k)) {
                        const int idx = (k << 7) + (lane << 2);
                        uint4 v = ld_rlx_v4(&g_w[rb][idx]);
                        unsigned bad = ((v.x ^ esbit) | (v.y ^ esbit) |
                                        (v.z ^ esbit) | (v.w ^ esbit)) & 0x80000000u;
                        if (!bad) {
                            float4 f;
                            f.x = __uint_as_float(v.x & 0x7fffffffu);
                            f.y = __uint_as_float(v.y & 0x7fffffffu);
                            f.z = __uint_as_float(v.z & 0x7fffffffu);
                            f.w = __uint_as_float(v.w & 0x7fffffffu);
                            *reinterpret_cast<float4*>(&w_s[par][idx]) = f;
                            mloc = fmaxf(mloc, fmaxf(fmaxf(f.x, f.y), fmaxf(f.z, f.w)));
                            pend &= ~(1u << k);
                        }
                    }
                }
            } while (__any_sync(0xffffffffu, pend));
            if (resc) {
                #pragma unroll
                for (int off = 16; off; off >>= 1)
                    mloc = fmaxf(mloc, __shfl_xor_sync(0xffffffffu, mloc, off));
                if (lane == 0) m_s[par] = mloc;
            }
        } else if (lane < 2) {
            // Other warps: prefetch emission two steps ahead while warp 0 polls.
            int tn = (t + 2 < TT) ? t + 2 : TT - 1;
            e_n2 = __ldg(&g_emitT[tn * S + col0 + lane]);
        }
        __syncthreads();

        if (wid == 0 && lane < 2) {
            int tn = (t + 2 < TT) ? t + 2 : TT - 1;
            e_n2 = __ldg(&g_emitT[tn * S + col0 + lane]);
        }

        float inv = 1.0f;
        if (resc) {
            float m = m_s[par];
            inv = 1.0f / m;
            logscale += logf(m);
        }

        // ---- GEMV: 2 full columns per warp, 1024 sources from SMEM ----
        float a0 = 0.f, b0 = 0.f, a1 = 0.f, b1 = 0.f;
        #pragma unroll
        for (int k = 0; k < 8; ++k) {
            const float4 wv = *reinterpret_cast<const float4*>(&w_s[par][(k << 7) + (lane << 2)]);
            const int p = k << 2;
            a0 += wv.x * P0[p]     + wv.y * P0[p + 1];
            b0 += wv.z * P0[p + 2] + wv.w * P0[p + 3];
            a1 += wv.x * P1[p]     + wv.y * P1[p + 1];
            b1 += wv.z * P1[p + 2] + wv.w * P1[p + 3];
        }
        float s0 = a0 + b0, s1 = a1 + b1;
        #pragma unroll
        for (int off = 16; off; off >>= 1) {
            s0 += __shfl_xor_sync(0xffffffffu, s0, off);
            s1 += __shfl_xor_sync(0xffffffffu, s1, off);
        }

        if (lane < 2) {
            float sv = (lane == 0) ? s0 : s1;
            float outv = fmaxf(sv * inv * e_c, 1e-33f);
            unsigned tagged = __float_as_uint(outv) | ((((unsigned)t >> 1) & 1u) << 31);
            st_rlx_u32(&g_w[t & 1][col0 + lane], tagged);
            e_c = e_n;
            e_n = e_n2;
        }
    }

    // ---- Epilogue: CTA 0 / warp 0 polls the final vector and reduces ----
    if (cta == 0 && wid == 0) {
        const unsigned esbit = (((unsigned)(TT - 1) >> 1) & 1u) << 31;
        const int rb = (TT - 1) & 1;
        unsigned pend = 0xffu;
        float s = 0.0f;
        do {
            #pragma unroll
            for (int k = 0; k < 8; ++k) {
                if (pend & (1u << k)) {
                    const int idx = (k << 7) + (lane << 2);
                    uint4 v = ld_rlx_v4(&g_w[rb][idx]);
                    unsigned bad = ((v.x ^ esbit) | (v.y ^ esbit) |
                                    (v.z ^ esbit) | (v.w ^ esbit)) & 0x80000000u;
                    if (!bad) {
                        s += __uint_as_float(v.x & 0x7fffffffu)
                           + __uint_as_float(v.y & 0x7fffffffu)
                           + __uint_as_float(v.z & 0x7fffffffu)
                           + __uint_as_float(v.w & 0x7fffffffu);
                        pend &= ~(1u << k);
                    }
                }
            }
        } while (__any_sync(0xffffffffu, pend));
        #pragma unroll
        for (int off = 16; off; off >>= 1)
            s += __shfl_xor_sync(0xffffffffu, s, off);
        if (lane == 0) out[0] = logf(s) + logscale;
    }
}

extern "C" void kernel_launch(void* const* d_in, const int* in_sizes, int n_in,
                              void* d_out, int out_size) {
    const int*   obs   = (const int*)d_in[0];
    const float* start = (const float*)d_in[1];
    const float* trans = (const float*)d_in[2];
    const float* emit  = (const float*)d_in[3];
    float*       out   = (float*)d_out;

    (void)in_sizes; (void)n_in; (void)out_size;

    const int init_blocks = (TT * S + 255) / 256;
    hmm_init_kernel<<<init_blocks, 256>>>(obs, start, emit);
    hmm_main_kernel<<<KCTA, NTHR>>>(trans, out);
}

// round 11
// speedup vs baseline: 2.6486x; 1.6197x over previous
#include <cuda_runtime.h>
#include <cuda_bf16.h>

// HMM forward, scaled probability domain.
//   w_t[j] = (sum_i w_{t-1}[i] * exp(trans[i,j])) * inv_norm * exp(emit[j,obs[t]])
//   out    = log(sum_j w_final[j]) + sum log(norm)
//
// R8: counter-release protocol (the only scheme both correct AND fast across
// R1-R7), minimized: 64 persistent CTAs x 256 threads, CTA owns 16 columns.
//  - ONE strong poller per CTA (tid 0, ld.acquire.gpu on a counter);
//    everyone else uses plain cached loads. Acquire-by-one + __syncthreads
//    invalidates the SM's L1 -> plain loads are coherent (R1-proven, 1e-7).
//  - Each thread loads its own 16B w-granule straight into GEMV registers
//    (no SMEM staging of w).
//  - Step uses 2 full barriers + 1 __syncwarp (finalize lanes and the
//    releasing lane are all in warp 0; syncwarp fences lanes 1-15's STGs
//    before lane 0's red.release.gpu).
//  - Rescale every 8 steps folded into the finalize.

#define S     1024
#define NOBS  4096
#define TT    8192
#define KCTA  64
#define CCOL  16
#define NTHR  256
#define NWARP (NTHR / 32)

__device__ __align__(16) float        g_emitT[TT * S];  // exp(emit[j, obs[t]]), [t][j]
__device__ __align__(16) float        g_w[2][S];        // double-buffered state vector
__device__ unsigned int g_counter;

__device__ __forceinline__ void red_release_add(unsigned int* p) {
    asm volatile("red.release.gpu.global.add.u32 [%0], 1;" :: "l"(p) : "memory");
}
__device__ __forceinline__ unsigned int ld_acquire(const unsigned int* p) {
    unsigned int v;
    asm volatile("ld.acquire.gpu.global.u32 %0, [%1];" : "=r"(v) : "l"(p) : "memory");
    return v;
}

// Prologue: gather exp(emit) per timestep, init w0, reset counter (every replay).
__global__ void hmm_init_kernel(const int* __restrict__ obs,
                                const float* __restrict__ start,
                                const float* __restrict__ emit) {
    long idx = (long)blockIdx.x * blockDim.x + threadIdx.x;
    if (idx == 0) g_counter = 0u;
    if (idx >= (long)TT * S) return;
    int t = (int)(idx >> 10);
    int j = (int)(idx & (S - 1));
    float e = expf(emit[(long)j * NOBS + obs[t]]);
    g_emitT[idx] = e;
    if (t == 0) g_w[0][j] = expf(start[j]) * e;
}

__global__ void __launch_bounds__(NTHR, 1)
hmm_main_kernel(const float* __restrict__ trans, float* __restrict__ out) {
    __shared__ float red_s[2][NWARP][CCOL];   // per-warp partials, parity-buffered
    __shared__ float max_s[2][NWARP];         // per-warp maxima,   parity-buffered

    const int tid  = threadIdx.x;
    const int lane = tid & 31;
    const int wid  = tid >> 5;
    const int cta  = blockIdx.x;
    const int j0   = cta * CCOL;
    const int i0   = tid << 2;                // this thread's 4 source states

    // P slice in registers: P[c][u] = exp(trans[i0+u][j0+c]).
    // Row segment j0..j0+15 is contiguous -> 4x float4 per source row.
    float P[CCOL][4];
    #pragma unroll
    for (int u = 0; u < 4; ++u) {
        const float* row = &trans[(long)(i0 + u) * S + j0];
        #pragma unroll
        for (int q = 0; q < 4; ++q) {
            float4 v = __ldg(reinterpret_cast<const float4*>(row + 4 * q));
            P[4 * q + 0][u] = expf(v.x);
            P[4 * q + 1][u] = expf(v.y);
            P[4 * q + 2][u] = expf(v.z);
            P[4 * q + 3][u] = expf(v.w);
        }
    }

    float e_c = 0.0f, e_n = 0.0f, e_n2 = 0.0f;
    if (tid < CCOL) {
        e_c = __ldg(&g_emitT[1 * S + j0 + tid]);
        e_n = __ldg(&g_emitT[2 * S + j0 + tid]);
    }

    float logscale = 0.0f;                    // identical across tid < CCOL

    for (int t = 1; t < TT; ++t) {
        const int  rb   = (t - 1) & 1;
        const int  par  = t & 1;
        const bool resc = ((t - 1) & 7) == 0;

        // ---- Load own 16B granule: coherent (acquire+bar ended prior step) ----
        const float4 wv = *reinterpret_cast<const float4*>(&g_w[rb][i0]);

        // Emission prefetch, two steps deep.
        if (tid < CCOL) {
            int tn = (t + 2 < TT) ? t + 2 : TT - 1;
            e_n2 = __ldg(&g_emitT[tn * S + j0 + tid]);
        }

        // ---- Rescale pre-pass (every 8th step) ----
        if (resc) {
            float m = fmaxf(fmaxf(wv.x, wv.y), fmaxf(wv.z, wv.w));
            #pragma unroll
            for (int off = 16; off; off >>= 1)
                m = fmaxf(m, __shfl_xor_sync(0xffffffffu, m, off));
            if (lane == 0) max_s[par][wid] = m;
        }

        // ---- GEMV: 64 FFMA, 16 independent chains ----
        float acc[CCOL];
        #pragma unroll
        for (int c = 0; c < CCOL; ++c)
            acc[c] = wv.x * P[c][0] + wv.y * P[c][1] + wv.z * P[c][2] + wv.w * P[c][3];

        #pragma unroll
        for (int off = 16; off; off >>= 1) {
            #pragma unroll
            for (int c = 0; c < CCOL; ++c)
                acc[c] += __shfl_xor_sync(0xffffffffu, acc[c], off);
        }
        if (lane == 0) {
            #pragma unroll
            for (int c = 0; c < CCOL; ++c) red_s[par][wid][c] = acc[c];
        }
        __syncthreads();                       // bar 1: partials visible

        // ---- Finalize (warp 0, lanes 0-15) + release + poll ----
        if (wid == 0) {
            if (lane < CCOL) {
                float inv = 1.0f;
                if (resc) {
                    float m = max_s[par][0];
                    #pragma unroll
                    for (int ww = 1; ww < NWARP; ++ww)
                        m = fmaxf(m, max_s[par][ww]);
                    inv = 1.0f / m;
                    logscale += logf(m);
                }
                float s = 0.0f;
                #pragma unroll
                for (int ww = 0; ww < NWARP; ++ww) s += red_s[par][ww][lane];
                g_w[t & 1][j0 + lane] = s * inv * e_c;
                e_c = e_n;
                e_n = e_n2;
            }
            __syncwarp();                      // fences lanes 1-15 STGs before release
            if (lane == 0) {
                red_release_add(&g_counter);
                const unsigned tgt = (unsigned)KCTA * (unsigned)t;
                while (ld_acquire(&g_counter) < tgt) { }
            }
        }
        __syncthreads();                       // bar 2: releases CTA into step t+1
    }

    // ---- Epilogue: CTA 0 reduces the final vector ----
    if (cta == 0) {
        const float4 fv = *reinterpret_cast<const float4*>(&g_w[(TT - 1) & 1][i0]);
        float s = fv.x + fv.y + fv.z + fv.w;
        #pragma unroll
        for (int off = 16; off; off >>= 1)
            s += __shfl_xor_sync(0xffffffffu, s, off);
        __shared__ float fin_s[NWARP];
        if (lane == 0) fin_s[wid] = s;
        __syncthreads();
        if (tid == 0) {
            float tot = 0.0f;
            #pragma unroll
            for (int ww = 0; ww < NWARP; ++ww) tot += fin_s[ww];
            out[0] = logf(tot) + logscale;
        }
    }
}

extern "C" void kernel_launch(void* const* d_in, const int* in_sizes, int n_in,
                              void* d_out, int out_size) {
    const int*   obs   = (const int*)d_in[0];
    const float* start = (const float*)d_in[1];
    const float* trans = (const float*)d_in[2];
    const float* emit  = (const float*)d_in[3];
    float*       out   = (float*)d_out;

    (void)in_sizes; (void)n_in; (void)out_size;

    const int init_blocks = (TT * S + 255) / 256;
    hmm_init_kernel<<<init_blocks, 256>>>(obs, start, emit);
    hmm_main_kernel<<<KCTA, NTHR>>>(trans, out);
}